// round 14
// baseline (speedup 1.0000x reference)
#include <cuda_runtime.h>
#include <cfloat>
#include <cstdint>

#define R_    512
#define K_    17
#define HIN   56
#define OUT   96
#define NT    256
#define GRID  888                  // 148 SMs x 6 CTAs: one persistent wave
#define NMAP  (R_ * K_)
#define TS    56                   // tmp row stride (words)
#define MPAD  2                    // s_mask replicated border rows each side

// ---- compile-time bicubic helpers (period 12 for 56->96) ----
__host__ __device__ constexpr float cubicw_c(float x) {
    x = x < 0.f ? -x : x;
    float nearw = (1.25f * x - 2.25f) * x * x + 1.0f;
    float farw  = -0.75f * (((x - 5.0f) * x + 8.0f) * x - 4.0f);
    return x <= 1.0f ? nearw : farw;
}
__host__ __device__ constexpr float srcf(int t) {
    return ((float)t + 0.5f) * (56.0f / 96.0f) - 0.5f;
}
__host__ __device__ constexpr int ifloorf_c(float x) {
    int i = (int)x;
    return ((float)i > x) ? i - 1 : i;
}
__host__ __device__ constexpr int bofs(int t) { return ifloorf_c(srcf(t)); }
__host__ __device__ constexpr int brel(int T) { return 7 * (T / 12) + bofs(T % 12); }
__host__ __device__ constexpr float wgt(int t, int k) {
    return cubicw_c(srcf(t) - (float)(bofs(t) - 1 + k));
}
__host__ __device__ constexpr int slot(int R) { return ((R % 4) + 4) % 4; }
__host__ __device__ constexpr int clampi(int v, int lo, int hi) {
    return v < lo ? lo : (v > hi ? hi : v);
}

struct WTab { float w[12][4]; int b[12]; };
__host__ __device__ constexpr WTab make_wtab() {
    WTab r{};
    for (int t = 0; t < 12; ++t) {
        r.b[t] = bofs(t);
        for (int k = 0; k < 4; ++k) r.w[t][k] = wgt(t, k);
    }
    return r;
}
__constant__ WTab cWT = make_wtab();

// ---- cp.async helpers ----
__device__ __forceinline__ void cp16(unsigned int sdst, const void* gsrc) {
    asm volatile("cp.async.cg.shared.global [%0], [%1], 16;" :: "r"(sdst), "l"(gsrc));
}
__device__ __forceinline__ void cp_commit() { asm volatile("cp.async.commit_group;"); }
__device__ __forceinline__ void cp_wait0() { asm volatile("cp.async.wait_group 0;"); }

// prefetch the 56x56 mask into padded smem (rows -2..57, stride 56 words).
// pad rows: -2,-1 := row 0 ; 56,57 := row 55 (border replicate, bit-identical).
__device__ __forceinline__ void prefetch_mask(unsigned int smask_u,
                                              const float* __restrict__ masks,
                                              int map, int tid) {
    const float4* g = (const float4*)(masks + (size_t)map * (HIN * HIN));
    const unsigned int body = smask_u + MPAD * HIN * 4;   // mask row 0 at padded row 2
    #pragma unroll
    for (int i = 0; i < 3; i++)
        cp16(body + (tid + i * NT) * 16, g + tid + i * NT);
    if (tid < 16)
        cp16(body + (768 + tid) * 16, g + 768 + tid);
    if (tid >= 32 && tid < 88) {
        int j = tid - 32;             // 0..55
        int p = j / 14;               // 0,1: top pad rows; 2,3: bottom pad rows
        int q = j - p * 14;
        if (p < 2) cp16(smask_u + (p * HIN + 4 * q) * 4, g + q);          // rows 0,1 <- mask row 0
        else       cp16(smask_u + ((56 + p) * HIN + 4 * q) * 4, g + 770 + q); // rows 58,59 <- row 55
    }
}

// -------- pass 1: vertical 56->96, float4 lanes, cyclic window, no clamps ---
template<int T, int T0, int TEND>
__device__ __forceinline__ void p1_team(
    float4 (&r)[4], const float* __restrict__ smg, float* __restrict__ dst)
{
    if constexpr (T < TEND) {
        constexpr int b = bofs(T);
        if constexpr (T == T0) {
            r[slot(b - 1)] = *(const float4*)(smg + (b - 1) * HIN);
            r[slot(b    )] = *(const float4*)(smg + (b    ) * HIN);
            r[slot(b + 1)] = *(const float4*)(smg + (b + 1) * HIN);
            r[slot(b + 2)] = *(const float4*)(smg + (b + 2) * HIN);
        } else if constexpr (bofs(T) != bofs(T - 1)) {
            r[slot(b + 2)] = *(const float4*)(smg + (b + 2) * HIN);
        }
        constexpr int s0 = slot(b - 1), s1 = slot(b), s2 = slot(b + 1), s3 = slot(b + 2);
        constexpr float W0 = wgt(T, 0), W1 = wgt(T, 1), W2 = wgt(T, 2), W3 = wgt(T, 3);
        float4 v;
        v.x = fmaf(r[s3].x, W3, fmaf(r[s2].x, W2, fmaf(r[s1].x, W1, r[s0].x * W0)));
        v.y = fmaf(r[s3].y, W3, fmaf(r[s2].y, W2, fmaf(r[s1].y, W1, r[s0].y * W0)));
        v.z = fmaf(r[s3].z, W3, fmaf(r[s2].z, W2, fmaf(r[s1].z, W1, r[s0].z * W0)));
        v.w = fmaf(r[s3].w, W3, fmaf(r[s2].w, W2, fmaf(r[s1].w, W1, r[s0].w * W0)));
        *(float4*)(dst + T * TS) = v;
        p1_team<T + 1, T0, TEND>(r, smg, dst);
    }
}

// ---------------- pass 2: JIT chunk loads, compile-time clamped taps --------
template<int T, int HALF>
__host__ __device__ constexpr int hiword() {
    return HALF == 0 ? (brel(T) + 2) : clampi(brel(T) + 6, 0, 31);
}
template<int C, int HI>
__device__ __forceinline__ void p2chunks(float* __restrict__ row, const float4* __restrict__ src) {
    if constexpr (C <= HI) {
        float4 q = src[C];
        row[4 * C + 0] = q.x; row[4 * C + 1] = q.y;
        row[4 * C + 2] = q.z; row[4 * C + 3] = q.w;
        p2chunks<C + 1, HI>(row, src);
    }
}
template<int T, int HALF>
__device__ __forceinline__ void p2load(float* __restrict__ row, const float4* __restrict__ src) {
    constexpr int hi = hiword<T, HALF>() / 4;
    constexpr int lo = (T == 0) ? 0 : hiword<T - 1, HALF>() / 4 + 1;
    p2chunks<lo, hi>(row, src);
}
template<int T, int HALF>
__device__ __forceinline__ float p2v(const float* __restrict__ row) {
    constexpr int t = T % 12;
    constexpr int i0 = (HALF == 0) ? clampi(brel(T) - 1, 0, 31) : clampi(brel(T) + 3, 0, 31);
    constexpr int i1 = (HALF == 0) ? clampi(brel(T)    , 0, 31) : clampi(brel(T) + 4, 0, 31);
    constexpr int i2 = (HALF == 0) ? clampi(brel(T) + 1, 0, 31) : clampi(brel(T) + 5, 0, 31);
    constexpr int i3 = (HALF == 0) ? clampi(brel(T) + 2, 0, 31) : clampi(brel(T) + 6, 0, 31);
    constexpr float W0 = wgt(t, 0), W1 = wgt(t, 1), W2 = wgt(t, 2), W3 = wgt(t, 3);
    return fmaf(row[i3], W3, fmaf(row[i2], W2, fmaf(row[i1], W1, row[i0] * W0)));
}
template<int G, int HALF>
__device__ __forceinline__ void p2super(
    float* __restrict__ row, const float4* __restrict__ src,
    float& best, int& bestGS, int baseIdx)
{
    if constexpr (G < 6) {
        p2load<8 * G + 0, HALF>(row, src); float v0 = p2v<8 * G + 0, HALF>(row);
        p2load<8 * G + 1, HALF>(row, src); float v1 = p2v<8 * G + 1, HALF>(row);
        p2load<8 * G + 2, HALF>(row, src); float v2 = p2v<8 * G + 2, HALF>(row);
        p2load<8 * G + 3, HALF>(row, src); float v3 = p2v<8 * G + 3, HALF>(row);
        p2load<8 * G + 4, HALF>(row, src); float v4 = p2v<8 * G + 4, HALF>(row);
        p2load<8 * G + 5, HALF>(row, src); float v5 = p2v<8 * G + 5, HALF>(row);
        p2load<8 * G + 6, HALF>(row, src); float v6 = p2v<8 * G + 6, HALF>(row);
        p2load<8 * G + 7, HALF>(row, src); float v7 = p2v<8 * G + 7, HALF>(row);
        float gm = fmaxf(fmaxf(fmaxf(v0, v1), fmaxf(v2, v3)),
                         fmaxf(fmaxf(v4, v5), fmaxf(v6, v7)));
        if (gm > best) { best = gm; bestGS = baseIdx + 8 * G; } // strict '>': earliest group
        p2super<G + 1, HALF>(row, src, best, bestGS, baseIdx);
    }
}

__global__ void __launch_bounds__(NT, 6) kp_kernel(
    const float* __restrict__ masks,
    const float* __restrict__ boxes,
    float* __restrict__ out)
{
    __shared__ float s_mask[(HIN + 2 * MPAD) * HIN];  // 13.4 KB, padded rows
    __shared__ float s_tmp[OUT * TS];                 // 21 KB
    __shared__ float s_rv[NT / 32];
    __shared__ int   s_ri[NT / 32];

    const int tid = threadIdx.x;
    unsigned int smask_u = (unsigned int)__cvta_generic_to_shared(s_mask);

    prefetch_mask(smask_u, masks, blockIdx.x, tid);
    cp_commit();

    // persistent loop: one wave of 888 CTAs, map stride 888
    for (int map = blockIdx.x; map < NMAP; map += GRID) {
        const int r_ = map / K_;
        const int k_ = map - r_ * K_;
        const float4 bx = *(const float4*)(boxes + r_ * 4);   // hoisted box load

        cp_wait0();
        __syncthreads();    // mask visible; s_tmp/s_rv free

        // ---- pass 1: warp-aligned teams (warps 0-3: T=0..5, warps 4-7: T=6..11) ----
        {
            int team = tid >> 7;             // 0 or 1, warp-uniform
            int rr   = tid & 127;            // lane within team
            if (rr < 112) {
                int g = rr / 14;             // 0..7 period block
                int q = rr - g * 14;         // 0..13 column quad
                const float* smg = s_mask + (MPAD + 7 * g) * HIN + 4 * q;
                float* dst = s_tmp + (12 * g) * TS + 4 * q;
                float4 rwin[4];
                if (team == 0) p1_team<0, 0, 6 >(rwin, smg, dst);
                else           p1_team<6, 6, 12>(rwin, smg, dst);
            }
        }
        __syncthreads();

        // ---- prefetch next map's mask (overlaps pass 2) ----
        if (map + GRID < NMAP) prefetch_mask(smask_u, masks, map + GRID, tid);
        cp_commit();

        // ---- pass 2: horizontal 56->96 with supergrouped argmax ----
        float best = -FLT_MAX;
        int bestGS = 0x7fffffff;
        if (tid < 192) {
            int half = tid / 96;             // warp-uniform
            int h    = tid - half * 96;
            float row[32];
            if (half == 0) {
                const float4* src = (const float4*)(s_tmp + h * TS);
                p2super<0, 0>(row, src, best, bestGS, h * OUT);
            } else {
                const float4* src = (const float4*)(s_tmp + h * TS + 24);
                p2super<0, 1>(row, src, best, bestGS, h * OUT + 48);
            }
        }

        #pragma unroll
        for (int off = 16; off > 0; off >>= 1) {
            float ov = __shfl_down_sync(0xffffffffu, best, off);
            int   og = __shfl_down_sync(0xffffffffu, bestGS, off);
            if (ov > best || (ov == best && og < bestGS)) { best = ov; bestGS = og; }
        }
        if ((tid & 31) == 0) { s_rv[tid >> 5] = best; s_ri[tid >> 5] = bestGS; }
        __syncthreads();

        // ---- distributed tail: warp 0 reduces partials + parallel recovery ----
        if (tid < 32) {
            int lane = tid;
            float bv = (lane < NT / 32) ? s_rv[lane] : -FLT_MAX;
            int   bg = (lane < NT / 32) ? s_ri[lane] : 0x7fffffff;
            #pragma unroll
            for (int off = 4; off > 0; off >>= 1) {
                float ov = __shfl_down_sync(0xffffffffu, bv, off);
                int   og = __shfl_down_sync(0xffffffffu, bg, off);
                if (ov > bv || (ov == bv && og < bg)) { bv = ov; bg = og; }
            }
            float bestAll = __shfl_sync(0xffffffffu, bv, 0);
            int   gs      = __shfl_sync(0xffffffffu, bg, 0);

            int hh = gs / OUT;
            int w0 = gs - hh * OUT;
            float v = -FLT_MAX;
            if (lane < 8) {      // lanes recompute the 8 candidates in parallel
                int T = w0 + lane;
                int d = T / 12;
                int t = T - 12 * d;
                int base = 7 * d + cWT.b[t] - 1;
                const float* rowp = s_tmp + hh * TS;
                float x0 = rowp[min(max(base + 0, 0), 55)];
                float x1 = rowp[min(max(base + 1, 0), 55)];
                float x2 = rowp[min(max(base + 2, 0), 55)];
                float x3 = rowp[min(max(base + 3, 0), 55)];
                v = fmaf(x3, cWT.w[t][3],
                    fmaf(x2, cWT.w[t][2],
                    fmaf(x1, cWT.w[t][1], x0 * cWT.w[t][0])));
            }
            unsigned ball = __ballot_sync(0xffffffffu, v == bestAll);
            int found = __ffs(ball) - 1;     // lowest lane = first (smallest) index

            if (lane == 0) {
                int bestIdx = gs + found;
                float len0 = fmaxf(bx.z - bx.x, 1.0f);
                float len1 = fmaxf(bx.w - bx.y, 1.0f);
                int y = bestIdx / OUT;
                int x = bestIdx - y * OUT;
                float p0 = ((float)y + 0.5f) * (len0 / (float)OUT) + bx.x;
                float p1 = ((float)x + 0.5f) * (len1 / (float)OUT) + bx.y;

                float* pred   = out;                    // [R, 3, K]
                float* scores = out + R_ * 3 * K_;      // [R, K]
                pred[r_ * 3 * K_ + 0 * K_ + k_] = p0;
                pred[r_ * 3 * K_ + 1 * K_ + k_] = p1;
                pred[r_ * 3 * K_ + 2 * K_ + k_] = 1.0f;
                scores[r_ * K_ + k_] = bestAll;
            }
        }
    }
}

extern "C" void kernel_launch(void* const* d_in, const int* in_sizes, int n_in,
                              void* d_out, int out_size) {
    const float* masks = (const float*)d_in[0];   // [512,17,56,56] f32
    const float* boxes = (const float*)d_in[1];   // [512,4] f32
    float* out = (float*)d_out;
    kp_kernel<<<GRID, NT>>>(masks, boxes, out);
}

// round 15
// speedup vs baseline: 1.0439x; 1.0439x over previous
#include <cuda_runtime.h>
#include <cfloat>
#include <cstdint>

#define R_    512
#define K_    17
#define HIN   56
#define OUT   96
#define NT    192
#define MPC   4                    // maps per CTA
#define NMAP  (R_ * K_)
#define TS    56                   // tmp row stride (words)
#define MPAD  2                    // s_mask replicated border rows each side

// ---- compile-time bicubic helpers (period 12 for 56->96) ----
__host__ __device__ constexpr float cubicw_c(float x) {
    x = x < 0.f ? -x : x;
    float nearw = (1.25f * x - 2.25f) * x * x + 1.0f;
    float farw  = -0.75f * (((x - 5.0f) * x + 8.0f) * x - 4.0f);
    return x <= 1.0f ? nearw : farw;
}
__host__ __device__ constexpr float srcf(int t) {
    return ((float)t + 0.5f) * (56.0f / 96.0f) - 0.5f;
}
__host__ __device__ constexpr int ifloorf_c(float x) {
    int i = (int)x;
    return ((float)i > x) ? i - 1 : i;
}
__host__ __device__ constexpr int bofs(int t) { return ifloorf_c(srcf(t)); }
__host__ __device__ constexpr int brel(int T) { return 7 * (T / 12) + bofs(T % 12); }
__host__ __device__ constexpr float wgt(int t, int k) {
    return cubicw_c(srcf(t) - (float)(bofs(t) - 1 + k));
}
__host__ __device__ constexpr int slot(int R) { return ((R % 4) + 4) % 4; }
__host__ __device__ constexpr int clampi(int v, int lo, int hi) {
    return v < lo ? lo : (v > hi ? hi : v);
}

struct WTab { float w[12][4]; int b[12]; };
__host__ __device__ constexpr WTab make_wtab() {
    WTab r{};
    for (int t = 0; t < 12; ++t) {
        r.b[t] = bofs(t);
        for (int k = 0; k < 4; ++k) r.w[t][k] = wgt(t, k);
    }
    return r;
}
__constant__ WTab cWT = make_wtab();

// ---- order-isomorphic packing for (value desc, index asc) argmax ----
__device__ __forceinline__ unsigned enc_f(float f) {
    unsigned u = __float_as_uint(f);
    return (u & 0x80000000u) ? ~u : (u | 0x80000000u);
}
__device__ __forceinline__ float dec_f(unsigned e) {
    return (e & 0x80000000u) ? __uint_as_float(e & 0x7fffffffu)
                             : __uint_as_float(~e);
}

// ---- cp.async helpers ----
__device__ __forceinline__ void cp16(unsigned int sdst, const void* gsrc) {
    asm volatile("cp.async.cg.shared.global [%0], [%1], 16;" :: "r"(sdst), "l"(gsrc));
}
__device__ __forceinline__ void cp_commit() { asm volatile("cp.async.commit_group;"); }
__device__ __forceinline__ void cp_wait0() { asm volatile("cp.async.wait_group 0;"); }

// prefetch the 56x56 mask into padded smem (rows -2..57, stride 56 words).
// pad rows: -2,-1 := row 0 ; 56,57 := row 55 (border replicate, bit-identical).
__device__ __forceinline__ void prefetch_mask(unsigned int smask_u,
                                              const float* __restrict__ masks,
                                              int map, int tid) {
    const float4* g = (const float4*)(masks + (size_t)map * (HIN * HIN));
    const unsigned int body = smask_u + MPAD * HIN * 4;   // mask row 0 at padded row 2
    #pragma unroll
    for (int i = 0; i < 4; i++)
        cp16(body + (tid + i * NT) * 16, g + tid + i * NT);
    if (tid < 16)
        cp16(body + (768 + tid) * 16, g + 768 + tid);
    if (tid >= 32 && tid < 88) {
        int j = tid - 32;             // 0..55
        int p = j / 14;               // 0,1: top pad rows; 2,3: bottom pad rows
        int q = j - p * 14;
        if (p < 2) cp16(smask_u + (p * HIN + 4 * q) * 4, g + q);              // rows 0,1 <- row 0
        else       cp16(smask_u + ((56 + p) * HIN + 4 * q) * 4, g + 770 + q); // rows 58,59 <- row 55
    }
}

// -------- pass 1: vertical 56->96, float4 lanes, cyclic window, no clamps ---
template<int T>
__device__ __forceinline__ void p1_all(
    float4 (&r)[4], const float* __restrict__ smg, float* __restrict__ dst)
{
    if constexpr (T < 12) {
        constexpr int b = bofs(T);
        if constexpr (T == 0) {
            r[slot(b - 1)] = *(const float4*)(smg + (b - 1) * HIN);
            r[slot(b    )] = *(const float4*)(smg + (b    ) * HIN);
            r[slot(b + 1)] = *(const float4*)(smg + (b + 1) * HIN);
            r[slot(b + 2)] = *(const float4*)(smg + (b + 2) * HIN);
        } else if constexpr (bofs(T) != bofs(T - 1)) {
            r[slot(b + 2)] = *(const float4*)(smg + (b + 2) * HIN);
        }
        constexpr int s0 = slot(b - 1), s1 = slot(b), s2 = slot(b + 1), s3 = slot(b + 2);
        constexpr float W0 = wgt(T, 0), W1 = wgt(T, 1), W2 = wgt(T, 2), W3 = wgt(T, 3);
        float4 v;
        v.x = fmaf(r[s3].x, W3, fmaf(r[s2].x, W2, fmaf(r[s1].x, W1, r[s0].x * W0)));
        v.y = fmaf(r[s3].y, W3, fmaf(r[s2].y, W2, fmaf(r[s1].y, W1, r[s0].y * W0)));
        v.z = fmaf(r[s3].z, W3, fmaf(r[s2].z, W2, fmaf(r[s1].z, W1, r[s0].z * W0)));
        v.w = fmaf(r[s3].w, W3, fmaf(r[s2].w, W2, fmaf(r[s1].w, W1, r[s0].w * W0)));
        *(float4*)(dst + T * TS) = v;
        p1_all<T + 1>(r, smg, dst);
    }
}

// ---------------- pass 2: JIT chunk loads, compile-time clamped taps --------
template<int T, int HALF>
__host__ __device__ constexpr int hiword() {
    return HALF == 0 ? (brel(T) + 2) : clampi(brel(T) + 6, 0, 31);
}
template<int C, int HI>
__device__ __forceinline__ void p2chunks(float* __restrict__ row, const float4* __restrict__ src) {
    if constexpr (C <= HI) {
        float4 q = src[C];
        row[4 * C + 0] = q.x; row[4 * C + 1] = q.y;
        row[4 * C + 2] = q.z; row[4 * C + 3] = q.w;
        p2chunks<C + 1, HI>(row, src);
    }
}
template<int T, int HALF>
__device__ __forceinline__ void p2load(float* __restrict__ row, const float4* __restrict__ src) {
    constexpr int hi = hiword<T, HALF>() / 4;
    constexpr int lo = (T == 0) ? 0 : hiword<T - 1, HALF>() / 4 + 1;
    p2chunks<lo, hi>(row, src);
}
template<int T, int HALF>
__device__ __forceinline__ float p2v(const float* __restrict__ row) {
    constexpr int t = T % 12;
    constexpr int i0 = (HALF == 0) ? clampi(brel(T) - 1, 0, 31) : clampi(brel(T) + 3, 0, 31);
    constexpr int i1 = (HALF == 0) ? clampi(brel(T)    , 0, 31) : clampi(brel(T) + 4, 0, 31);
    constexpr int i2 = (HALF == 0) ? clampi(brel(T) + 1, 0, 31) : clampi(brel(T) + 5, 0, 31);
    constexpr int i3 = (HALF == 0) ? clampi(brel(T) + 2, 0, 31) : clampi(brel(T) + 6, 0, 31);
    constexpr float W0 = wgt(t, 0), W1 = wgt(t, 1), W2 = wgt(t, 2), W3 = wgt(t, 3);
    return fmaf(row[i3], W3, fmaf(row[i2], W2, fmaf(row[i1], W1, row[i0] * W0)));
}
template<int G, int HALF>
__device__ __forceinline__ void p2super(
    float* __restrict__ row, const float4* __restrict__ src,
    float& best, int& bestGS, int baseIdx)
{
    if constexpr (G < 6) {
        p2load<8 * G + 0, HALF>(row, src); float v0 = p2v<8 * G + 0, HALF>(row);
        p2load<8 * G + 1, HALF>(row, src); float v1 = p2v<8 * G + 1, HALF>(row);
        p2load<8 * G + 2, HALF>(row, src); float v2 = p2v<8 * G + 2, HALF>(row);
        p2load<8 * G + 3, HALF>(row, src); float v3 = p2v<8 * G + 3, HALF>(row);
        p2load<8 * G + 4, HALF>(row, src); float v4 = p2v<8 * G + 4, HALF>(row);
        p2load<8 * G + 5, HALF>(row, src); float v5 = p2v<8 * G + 5, HALF>(row);
        p2load<8 * G + 6, HALF>(row, src); float v6 = p2v<8 * G + 6, HALF>(row);
        p2load<8 * G + 7, HALF>(row, src); float v7 = p2v<8 * G + 7, HALF>(row);
        float gm = fmaxf(fmaxf(fmaxf(v0, v1), fmaxf(v2, v3)),
                         fmaxf(fmaxf(v4, v5), fmaxf(v6, v7)));
        if (gm > best) { best = gm; bestGS = baseIdx + 8 * G; } // strict '>': earliest group
        p2super<G + 1, HALF>(row, src, best, bestGS, baseIdx);
    }
}

__global__ void __launch_bounds__(NT, 6) kp_kernel(
    const float* __restrict__ masks,
    const float* __restrict__ boxes,
    float* __restrict__ out)
{
    __shared__ float s_mask[(HIN + 2 * MPAD) * HIN];  // 13.4 KB, padded rows
    __shared__ float s_tmp[OUT * TS];                 // 21 KB
    __shared__ unsigned long long s_best;

    const int tid  = threadIdx.x;
    const int map0 = blockIdx.x * MPC;

    unsigned int smask_u = (unsigned int)__cvta_generic_to_shared(s_mask);

    prefetch_mask(smask_u, masks, map0, tid);
    cp_commit();

    for (int m = 0; m < MPC; m++) {
        const int map = map0 + m;
        const int r_  = map / K_;
        const int k_  = map - r_ * K_;
        float4 bx;
        if (tid < 32) bx = *(const float4*)(boxes + r_ * 4);  // only warp 0 needs it

        cp_wait0();
        __syncthreads();    // mask ready; s_tmp + s_best free (prev tail done)

        // ---- pass 1: 112 threads, (row-block g, column quad q), 12 steps ----
        if (tid < 112) {
            int g = tid / 14;          // 0..7 : 12 output rows each
            int q = tid - g * 14;      // 0..13: cols 4q..4q+3
            const float* smg = s_mask + (MPAD + 7 * g) * HIN + 4 * q;
            float* dst = s_tmp + (12 * g) * TS + 4 * q;
            float4 rwin[4];
            p1_all<0>(rwin, smg, dst);
        } else if (tid == 191) {
            s_best = 0ull;             // reset argmax accumulator for this map
        }
        __syncthreads();

        // ---- prefetch next map's mask (overlaps pass 2) ----
        if (m + 1 < MPC) prefetch_mask(smask_u, masks, map + 1, tid);
        cp_commit();

        // ---- pass 2: horizontal 56->96 with supergrouped argmax ----
        float best = -FLT_MAX;
        int bestGS = 0x7fffffff;
        {
            int half = tid / 96;             // warps 0-2: half 0, warps 3-5: half 1
            int h    = tid - half * 96;
            float row[32];
            if (half == 0) {
                const float4* src = (const float4*)(s_tmp + h * TS);
                p2super<0, 0>(row, src, best, bestGS, h * OUT);
            } else {
                const float4* src = (const float4*)(s_tmp + h * TS + 24);
                p2super<0, 1>(row, src, best, bestGS, h * OUT + 48);
            }
        }

        // warp-level reduce, then one packed atomicMax per warp
        #pragma unroll
        for (int off = 16; off > 0; off >>= 1) {
            float ov = __shfl_down_sync(0xffffffffu, best, off);
            int   og = __shfl_down_sync(0xffffffffu, bestGS, off);
            if (ov > best || (ov == best && og < bestGS)) { best = ov; bestGS = og; }
        }
        if ((tid & 31) == 0) {
            unsigned long long packed =
                ((unsigned long long)enc_f(best) << 32) | (unsigned)(~bestGS);
            atomicMax(&s_best, packed);
        }
        __syncthreads();

        // ---- tail: warp 0 decodes winner + parallel within-group recovery ----
        if (tid < 32) {
            unsigned long long packed = s_best;
            float bestAll = dec_f((unsigned)(packed >> 32));
            int   gs      = ~((unsigned)packed);

            int hh = gs / OUT;
            int w0 = gs - hh * OUT;
            float v = -FLT_MAX;
            if (tid < 8) {       // lanes recompute the 8 candidates in parallel
                int T = w0 + tid;
                int d = T / 12;
                int t = T - 12 * d;
                int base = 7 * d + cWT.b[t] - 1;
                const float* rowp = s_tmp + hh * TS;
                float x0 = rowp[min(max(base + 0, 0), 55)];
                float x1 = rowp[min(max(base + 1, 0), 55)];
                float x2 = rowp[min(max(base + 2, 0), 55)];
                float x3 = rowp[min(max(base + 3, 0), 55)];
                v = fmaf(x3, cWT.w[t][3],
                    fmaf(x2, cWT.w[t][2],
                    fmaf(x1, cWT.w[t][1], x0 * cWT.w[t][0])));
            }
            unsigned ball = __ballot_sync(0xffffffffu, v == bestAll);
            int found = __ffs(ball) - 1;     // lowest lane = first (smallest) index

            if (tid == 0) {
                int bestIdx = gs + found;
                float len0 = fmaxf(bx.z - bx.x, 1.0f);
                float len1 = fmaxf(bx.w - bx.y, 1.0f);
                int y = bestIdx / OUT;
                int x = bestIdx - y * OUT;
                float p0 = ((float)y + 0.5f) * (len0 / (float)OUT) + bx.x;
                float p1 = ((float)x + 0.5f) * (len1 / (float)OUT) + bx.y;

                float* pred   = out;                    // [R, 3, K]
                float* scores = out + R_ * 3 * K_;      // [R, K]
                pred[r_ * 3 * K_ + 0 * K_ + k_] = p0;
                pred[r_ * 3 * K_ + 1 * K_ + k_] = p1;
                pred[r_ * 3 * K_ + 2 * K_ + k_] = 1.0f;
                scores[r_ * K_ + k_] = bestAll;
            }
        }
    }
}

extern "C" void kernel_launch(void* const* d_in, const int* in_sizes, int n_in,
                              void* d_out, int out_size) {
    const float* masks = (const float*)d_in[0];   // [512,17,56,56] f32
    const float* boxes = (const float*)d_in[1];   // [512,4] f32
    float* out = (float*)d_out;
    kp_kernel<<<NMAP / MPC, NT>>>(masks, boxes, out);
}

// round 16
// speedup vs baseline: 1.1375x; 1.0896x over previous
#include <cuda_runtime.h>
#include <cfloat>
#include <cstdint>

#define R_    512
#define K_    17
#define HIN   56
#define OUT   96
#define NT    192
#define MPC   4                    // maps per CTA
#define NMAP  (R_ * K_)
#define TS    60                   // tmp stride: (60*h) mod 32 spans all 8 bank-groups
                                   // -> conflict-free LDS.128 in pass 2
#define MPAD  2                    // s_mask replicated border rows each side

// ---- compile-time bicubic helpers (period 12 for 56->96) ----
__host__ __device__ constexpr float cubicw_c(float x) {
    x = x < 0.f ? -x : x;
    float nearw = (1.25f * x - 2.25f) * x * x + 1.0f;
    float farw  = -0.75f * (((x - 5.0f) * x + 8.0f) * x - 4.0f);
    return x <= 1.0f ? nearw : farw;
}
__host__ __device__ constexpr float srcf(int t) {
    return ((float)t + 0.5f) * (56.0f / 96.0f) - 0.5f;
}
__host__ __device__ constexpr int ifloorf_c(float x) {
    int i = (int)x;
    return ((float)i > x) ? i - 1 : i;
}
__host__ __device__ constexpr int bofs(int t) { return ifloorf_c(srcf(t)); }
__host__ __device__ constexpr int brel(int T) { return 7 * (T / 12) + bofs(T % 12); }
__host__ __device__ constexpr float wgt(int t, int k) {
    return cubicw_c(srcf(t) - (float)(bofs(t) - 1 + k));
}
__host__ __device__ constexpr int slot(int R) { return ((R % 4) + 4) % 4; }
__host__ __device__ constexpr int clampi(int v, int lo, int hi) {
    return v < lo ? lo : (v > hi ? hi : v);
}

struct WTab { float w[12][4]; int b[12]; };
__host__ __device__ constexpr WTab make_wtab() {
    WTab r{};
    for (int t = 0; t < 12; ++t) {
        r.b[t] = bofs(t);
        for (int k = 0; k < 4; ++k) r.w[t][k] = wgt(t, k);
    }
    return r;
}
__constant__ WTab cWT = make_wtab();

// ---- order-isomorphic packing for (value desc, index asc) argmax ----
__device__ __forceinline__ unsigned enc_f(float f) {
    unsigned u = __float_as_uint(f);
    return (u & 0x80000000u) ? ~u : (u | 0x80000000u);
}
__device__ __forceinline__ float dec_f(unsigned e) {
    return (e & 0x80000000u) ? __uint_as_float(e & 0x7fffffffu)
                             : __uint_as_float(~e);
}

// ---- cp.async helpers ----
__device__ __forceinline__ void cp16(unsigned int sdst, const void* gsrc) {
    asm volatile("cp.async.cg.shared.global [%0], [%1], 16;" :: "r"(sdst), "l"(gsrc));
}
__device__ __forceinline__ void cp_commit() { asm volatile("cp.async.commit_group;"); }
__device__ __forceinline__ void cp_wait0() { asm volatile("cp.async.wait_group 0;"); }

// prefetch the 56x56 mask into padded smem (rows -2..57, stride 56 words).
// pad rows: -2,-1 := row 0 ; 56,57 := row 55 (border replicate, bit-identical).
__device__ __forceinline__ void prefetch_mask(unsigned int smask_u,
                                              const float* __restrict__ masks,
                                              int map, int tid) {
    const float4* g = (const float4*)(masks + (size_t)map * (HIN * HIN));
    const unsigned int body = smask_u + MPAD * HIN * 4;   // mask row 0 at padded row 2
    #pragma unroll
    for (int i = 0; i < 4; i++)
        cp16(body + (tid + i * NT) * 16, g + tid + i * NT);
    if (tid < 16)
        cp16(body + (768 + tid) * 16, g + 768 + tid);
    if (tid >= 32 && tid < 88) {
        int j = tid - 32;             // 0..55
        int p = j / 14;               // 0,1: top pad rows; 2,3: bottom pad rows
        int q = j - p * 14;
        if (p < 2) cp16(smask_u + (p * HIN + 4 * q) * 4, g + q);              // rows 0,1 <- row 0
        else       cp16(smask_u + ((56 + p) * HIN + 4 * q) * 4, g + 770 + q); // rows 58,59 <- row 55
    }
}

// -------- pass 1: vertical 56->96, float4 lanes, cyclic window, no clamps ---
template<int T>
__device__ __forceinline__ void p1_all(
    float4 (&r)[4], const float* __restrict__ smg, float* __restrict__ dst)
{
    if constexpr (T < 12) {
        constexpr int b = bofs(T);
        if constexpr (T == 0) {
            r[slot(b - 1)] = *(const float4*)(smg + (b - 1) * HIN);
            r[slot(b    )] = *(const float4*)(smg + (b    ) * HIN);
            r[slot(b + 1)] = *(const float4*)(smg + (b + 1) * HIN);
            r[slot(b + 2)] = *(const float4*)(smg + (b + 2) * HIN);
        } else if constexpr (bofs(T) != bofs(T - 1)) {
            r[slot(b + 2)] = *(const float4*)(smg + (b + 2) * HIN);
        }
        constexpr int s0 = slot(b - 1), s1 = slot(b), s2 = slot(b + 1), s3 = slot(b + 2);
        constexpr float W0 = wgt(T, 0), W1 = wgt(T, 1), W2 = wgt(T, 2), W3 = wgt(T, 3);
        float4 v;
        v.x = fmaf(r[s3].x, W3, fmaf(r[s2].x, W2, fmaf(r[s1].x, W1, r[s0].x * W0)));
        v.y = fmaf(r[s3].y, W3, fmaf(r[s2].y, W2, fmaf(r[s1].y, W1, r[s0].y * W0)));
        v.z = fmaf(r[s3].z, W3, fmaf(r[s2].z, W2, fmaf(r[s1].z, W1, r[s0].z * W0)));
        v.w = fmaf(r[s3].w, W3, fmaf(r[s2].w, W2, fmaf(r[s1].w, W1, r[s0].w * W0)));
        *(float4*)(dst + T * TS) = v;
        p1_all<T + 1>(r, smg, dst);
    }
}

// ---------------- pass 2: JIT chunk loads, compile-time clamped taps --------
template<int T, int HALF>
__host__ __device__ constexpr int hiword() {
    return HALF == 0 ? (brel(T) + 2) : clampi(brel(T) + 6, 0, 31);
}
template<int C, int HI>
__device__ __forceinline__ void p2chunks(float* __restrict__ row, const float4* __restrict__ src) {
    if constexpr (C <= HI) {
        float4 q = src[C];
        row[4 * C + 0] = q.x; row[4 * C + 1] = q.y;
        row[4 * C + 2] = q.z; row[4 * C + 3] = q.w;
        p2chunks<C + 1, HI>(row, src);
    }
}
template<int T, int HALF>
__device__ __forceinline__ void p2load(float* __restrict__ row, const float4* __restrict__ src) {
    constexpr int hi = hiword<T, HALF>() / 4;
    constexpr int lo = (T == 0) ? 0 : hiword<T - 1, HALF>() / 4 + 1;
    p2chunks<lo, hi>(row, src);
}
template<int T, int HALF>
__device__ __forceinline__ float p2v(const float* __restrict__ row) {
    constexpr int t = T % 12;
    constexpr int i0 = (HALF == 0) ? clampi(brel(T) - 1, 0, 31) : clampi(brel(T) + 3, 0, 31);
    constexpr int i1 = (HALF == 0) ? clampi(brel(T)    , 0, 31) : clampi(brel(T) + 4, 0, 31);
    constexpr int i2 = (HALF == 0) ? clampi(brel(T) + 1, 0, 31) : clampi(brel(T) + 5, 0, 31);
    constexpr int i3 = (HALF == 0) ? clampi(brel(T) + 2, 0, 31) : clampi(brel(T) + 6, 0, 31);
    constexpr float W0 = wgt(t, 0), W1 = wgt(t, 1), W2 = wgt(t, 2), W3 = wgt(t, 3);
    return fmaf(row[i3], W3, fmaf(row[i2], W2, fmaf(row[i1], W1, row[i0] * W0)));
}
template<int G, int HALF>
__device__ __forceinline__ void p2super(
    float* __restrict__ row, const float4* __restrict__ src,
    float& best, int& bestGS, int baseIdx)
{
    if constexpr (G < 6) {
        p2load<8 * G + 0, HALF>(row, src); float v0 = p2v<8 * G + 0, HALF>(row);
        p2load<8 * G + 1, HALF>(row, src); float v1 = p2v<8 * G + 1, HALF>(row);
        p2load<8 * G + 2, HALF>(row, src); float v2 = p2v<8 * G + 2, HALF>(row);
        p2load<8 * G + 3, HALF>(row, src); float v3 = p2v<8 * G + 3, HALF>(row);
        p2load<8 * G + 4, HALF>(row, src); float v4 = p2v<8 * G + 4, HALF>(row);
        p2load<8 * G + 5, HALF>(row, src); float v5 = p2v<8 * G + 5, HALF>(row);
        p2load<8 * G + 6, HALF>(row, src); float v6 = p2v<8 * G + 6, HALF>(row);
        p2load<8 * G + 7, HALF>(row, src); float v7 = p2v<8 * G + 7, HALF>(row);
        float gm = fmaxf(fmaxf(fmaxf(v0, v1), fmaxf(v2, v3)),
                         fmaxf(fmaxf(v4, v5), fmaxf(v6, v7)));
        if (gm > best) { best = gm; bestGS = baseIdx + 8 * G; } // strict '>': earliest group
        p2super<G + 1, HALF>(row, src, best, bestGS, baseIdx);
    }
}

__global__ void __launch_bounds__(NT, 6) kp_kernel(
    const float* __restrict__ masks,
    const float* __restrict__ boxes,
    float* __restrict__ out)
{
    __shared__ float s_mask[(HIN + 2 * MPAD) * HIN];  // 13.4 KB, padded rows
    __shared__ float s_tmp[OUT * TS];                 // 22.5 KB (stride 60)
    __shared__ unsigned long long s_best;

    const int tid  = threadIdx.x;
    const int map0 = blockIdx.x * MPC;

    unsigned int smask_u = (unsigned int)__cvta_generic_to_shared(s_mask);

    prefetch_mask(smask_u, masks, map0, tid);
    cp_commit();

    for (int m = 0; m < MPC; m++) {
        const int map = map0 + m;
        const int r_  = map / K_;
        const int k_  = map - r_ * K_;
        float4 bx;
        if (tid < 32) bx = *(const float4*)(boxes + r_ * 4);  // only warp 0 needs it

        cp_wait0();
        __syncthreads();    // mask ready; s_tmp + s_best free (prev tail done)

        // ---- pass 1: 112 threads, (row-block g, column quad q), 12 steps ----
        if (tid < 112) {
            int g = tid / 14;          // 0..7 : 12 output rows each
            int q = tid - g * 14;      // 0..13: cols 4q..4q+3
            const float* smg = s_mask + (MPAD + 7 * g) * HIN + 4 * q;
            float* dst = s_tmp + (12 * g) * TS + 4 * q;
            float4 rwin[4];
            p1_all<0>(rwin, smg, dst);
        } else if (tid == 191) {
            s_best = 0ull;             // reset argmax accumulator for this map
        }
        __syncthreads();

        // ---- prefetch next map's mask (overlaps pass 2) ----
        if (m + 1 < MPC) prefetch_mask(smask_u, masks, map + 1, tid);
        cp_commit();

        // ---- pass 2: horizontal 56->96 with supergrouped argmax ----
        float best = -FLT_MAX;
        int bestGS = 0x7fffffff;
        {
            int half = tid / 96;             // warps 0-2: half 0, warps 3-5: half 1
            int h    = tid - half * 96;
            float row[32];
            if (half == 0) {
                const float4* src = (const float4*)(s_tmp + h * TS);
                p2super<0, 0>(row, src, best, bestGS, h * OUT);
            } else {
                const float4* src = (const float4*)(s_tmp + h * TS + 24);
                p2super<0, 1>(row, src, best, bestGS, h * OUT + 48);
            }
        }

        // warp-level reduce, then one packed atomicMax per warp
        #pragma unroll
        for (int off = 16; off > 0; off >>= 1) {
            float ov = __shfl_down_sync(0xffffffffu, best, off);
            int   og = __shfl_down_sync(0xffffffffu, bestGS, off);
            if (ov > best || (ov == best && og < bestGS)) { best = ov; bestGS = og; }
        }
        if ((tid & 31) == 0) {
            unsigned long long packed =
                ((unsigned long long)enc_f(best) << 32) | (unsigned)(~bestGS);
            atomicMax(&s_best, packed);
        }
        __syncthreads();

        // ---- tail: warp 0 decodes winner + parallel within-group recovery ----
        if (tid < 32) {
            unsigned long long packed = s_best;
            float bestAll = dec_f((unsigned)(packed >> 32));
            int   gs      = ~((unsigned)packed);

            int hh = gs / OUT;
            int w0 = gs - hh * OUT;
            float v = -FLT_MAX;
            if (tid < 8) {       // lanes recompute the 8 candidates in parallel
                int T = w0 + tid;
                int d = T / 12;
                int t = T - 12 * d;
                int base = 7 * d + cWT.b[t] - 1;
                const float* rowp = s_tmp + hh * TS;
                float x0 = rowp[min(max(base + 0, 0), 55)];
                float x1 = rowp[min(max(base + 1, 0), 55)];
                float x2 = rowp[min(max(base + 2, 0), 55)];
                float x3 = rowp[min(max(base + 3, 0), 55)];
                v = fmaf(x3, cWT.w[t][3],
                    fmaf(x2, cWT.w[t][2],
                    fmaf(x1, cWT.w[t][1], x0 * cWT.w[t][0])));
            }
            unsigned ball = __ballot_sync(0xffffffffu, v == bestAll);
            int found = __ffs(ball) - 1;     // lowest lane = first (smallest) index

            if (tid == 0) {
                int bestIdx = gs + found;
                float len0 = fmaxf(bx.z - bx.x, 1.0f);
                float len1 = fmaxf(bx.w - bx.y, 1.0f);
                int y = bestIdx / OUT;
                int x = bestIdx - y * OUT;
                float p0 = ((float)y + 0.5f) * (len0 / (float)OUT) + bx.x;
                float p1 = ((float)x + 0.5f) * (len1 / (float)OUT) + bx.y;

                float* pred   = out;                    // [R, 3, K]
                float* scores = out + R_ * 3 * K_;      // [R, K]
                pred[r_ * 3 * K_ + 0 * K_ + k_] = p0;
                pred[r_ * 3 * K_ + 1 * K_ + k_] = p1;
                pred[r_ * 3 * K_ + 2 * K_ + k_] = 1.0f;
                scores[r_ * K_ + k_] = bestAll;
            }
        }
    }
}

extern "C" void kernel_launch(void* const* d_in, const int* in_sizes, int n_in,
                              void* d_out, int out_size) {
    const float* masks = (const float*)d_in[0];   // [512,17,56,56] f32
    const float* boxes = (const float*)d_in[1];   // [512,4] f32
    float* out = (float*)d_out;
    kp_kernel<<<NMAP / MPC, NT>>>(masks, boxes, out);
}